// round 13
// baseline (speedup 1.0000x reference)
#include <cuda_runtime.h>
#include <cuda_bf16.h>
typedef unsigned U;

__device__ U g_wpk[430080];
__device__ U g_seq[131072*192];
__device__ U g_ctx[131072*192];
__device__ U g_x  [131072*192];
__device__ U g_h  [131072*384];
__device__ U g_z  [65536*192];

__device__ __forceinline__ void split2(float a,float b,U&hw,U&lw){
  __nv_bfloat162 h=__floats2bfloat162_rn(a,b);
  float2 hf=__bfloat1622float2(h);
  __nv_bfloat162 l=__floats2bfloat162_rn(a-hf.x,b-hf.y);
  hw=*(U*)&h; lw=*(U*)&l;
}
__device__ __forceinline__ float2 un2(U hw,U lw){
  float2 a=__bfloat1622float2(*(__nv_bfloat162*)&hw);
  float2 b=__bfloat1622float2(*(__nv_bfloat162*)&lw);
  return make_float2(a.x+b.x,a.y+b.y);
}
__device__ __forceinline__ void mma16(float* d,U a0,U a1,U a2,U a3,U b0,U b1){
  asm volatile("mma.sync.aligned.m16n8k16.row.col.f32.bf16.bf16.f32 {%0,%1,%2,%3},{%4,%5,%6,%7},{%8,%9},{%0,%1,%2,%3};"
    :"+f"(d[0]),"+f"(d[1]),"+f"(d[2]),"+f"(d[3]):"r"(a0),"r"(a1),"r"(a2),"r"(a3),"r"(b0),"r"(b1));}
__device__ __forceinline__ void cpa16(U* dst,const U* src){
  U d=(U)__cvta_generic_to_shared(dst);
  asm volatile("cp.async.cg.shared.global [%0],[%1],16;"::"r"(d),"l"(src));}

// ---- one-shot weight packing: quad layout [chunk][(n*4+t4)*4 + {hi0,hi1,lo0,lo1}] ----
struct SJ { const float* s; int ldw,N,K,gm,off; };
struct Jobs { SJ j[11]; };
__global__ void k_splitall(Jobs A){
  SJ J=A.j[blockIdx.y];
  int kh=J.K/2, tot=J.N*kh;
  for(int i=blockIdx.x*blockDim.x+threadIdx.x;i<tot;i+=gridDim.x*blockDim.x){
    int n=i/kh,p=i%kh,c=p>>3,kp=p&7;
    int row=(n>>6)*J.gm+(n&63);
    U hw,lw; split2(J.s[row*J.ldw+2*p],J.s[row*J.ldw+2*p+1],hw,lw);
    U* b=g_wpk+J.off+c*(J.N*16)+(n*4+(kp&3))*4+(kp>>2);
    b[0]=hw; b[2]=lw;
  }
}

// load interleaved activation rows (KTOT words/row) into smem pitch ALD
template<int KTOT,int ALD>
__device__ __forceinline__ void load_act(U* As,const U* X,int xs2,int row0,int tid,int nrows){
  for(int u=tid;u<nrows*(KTOT/4);u+=blockDim.x){
    int r=u/(KTOT/4),cc=u%(KTOT/4);
    cpa16(As+r*ALD+cc*4,X+(long)(row0+r)*xs2+cc*4);
  }
}
__device__ __forceinline__ void load_act32(U* As,const float* X,int row0,int tid,int nrows){
  for(int u=tid;u<nrows*96;u+=blockDim.x){
    int r=u/96,cw=u%96;
    float2 v=*(const float2*)(X+(long)(row0+r)*192+2*cw);
    U hw,lw; split2(v.x,v.y,hw,lw);
    *(uint2*)(As+r*200+2*cw)=make_uint2(hw,lw);
  }
}

// acc[NT][4] += A(64 x KTOT, interleaved hi/lo in smem) @ W^T (quad-packed, streamed)
template<int KTOT,int NT,int ALD>
__device__ __forceinline__ void gemm_bf(float (*acc)[4],const U* As,
    const U* __restrict__ Wg,U* Wb,int tid){
  constexpr int CW=NT*256, NC=KTOT/16;
  int lane=tid&31,warp=tid>>5,wm=warp&3,wn=warp>>2,gid=lane>>2,t4=lane&3;
  #pragma unroll
  for(int i=0;i<NT;i++){acc[i][0]=0.f;acc[i][1]=0.f;acc[i][2]=0.f;acc[i][3]=0.f;}
  for(int u=tid;u<CW/4;u+=blockDim.x) cpa16(Wb+4*u,Wg+4*u);
  asm volatile("cp.async.commit_group;");
  for(int c=0;c<NC;c++){
    U* cur=Wb+(c&1)*CW; U* nxt=Wb+((c+1)&1)*CW;
    if(c+1<NC){
      const U* s=Wg+(c+1)*CW;
      for(int u=tid;u<CW/4;u+=blockDim.x) cpa16(nxt+4*u,s+4*u);
      asm volatile("cp.async.commit_group;");
      asm volatile("cp.async.wait_group 1;");
    } else asm volatile("cp.async.wait_group 0;");
    __syncthreads();
    const U* ab=As+(wm*16+gid)*ALD+c*16+t4*2;
    uint2 p0=*(const uint2*)ab, p1=*(const uint2*)(ab+8);
    uint2 p2=*(const uint2*)(ab+8*ALD), p3=*(const uint2*)(ab+8*ALD+8);
    const U* bb=cur+wn*(NT*8)*16+lane*4;
    #pragma unroll
    for(int nt=0;nt<NT;nt++){
      uint4 q=*(const uint4*)(bb+nt*128);
      mma16(acc[nt],p0.x,p2.x,p1.x,p3.x,q.x,q.y);
      mma16(acc[nt],p0.y,p2.y,p1.y,p3.y,q.x,q.y);
      mma16(acc[nt],p0.x,p2.x,p1.x,p3.x,q.z,q.w);
    }
    __syncthreads();
  }
}

// generic GEMM: Y = (relu?)(X@W^T+b), 64 rows/CTA, 192-col chunks via blockIdx.y
// interleaved layout: word offset == column index, row stride ys2 words
template<int SRC32>
__global__ __launch_bounds__(256,2) void k_gemm192(const float* X32,const U* X,int xs2,
    U* Y,int ys2,const U* __restrict__ Wpk,int wsz,const float* __restrict__ bias,int relu){
  extern __shared__ U sm[];
  U* As=sm; U* Wb=sm+12800;
  int tid=threadIdx.x,row0=blockIdx.x*64,n0=blockIdx.y*192;
  if(SRC32) load_act32(As,X32,row0,tid,64);
  else load_act<192,200>(As,X,xs2,row0,tid,64);
  asm volatile("cp.async.commit_group;");
  float acc[12][4];
  gemm_bf<192,12,200>(acc,As,Wpk+(long)blockIdx.y*wsz,Wb,tid);
  U* Yc=Y+(long)n0;   // word offset == column offset
  int lane=tid&31,warp=tid>>5,wm=warp&3,wn=warp>>2,gid=lane>>2,t4=lane&3;
  #pragma unroll
  for(int nt=0;nt<12;nt++){
    int n=wn*96+nt*8+2*t4,m=wm*16+gid;
    float b0=bias[n0+n],b1=bias[n0+n+1];
    float v0=acc[nt][0]+b0,v1=acc[nt][1]+b1,v2=acc[nt][2]+b0,v3=acc[nt][3]+b1;
    if(relu){v0=fmaxf(v0,0.f);v1=fmaxf(v1,0.f);v2=fmaxf(v2,0.f);v3=fmaxf(v3,0.f);}
    U hw,lw;
    split2(v0,v1,hw,lw); *(uint2*)(Yc+(long)(row0+m)*ys2+n)=make_uint2(hw,lw);
    split2(v2,v3,hw,lw); *(uint2*)(Yc+(long)(row0+m+8)*ys2+n)=make_uint2(hw,lw);
  }
}

// fused qkv (per-head gathered weights) + 2x2 attention -> ctx. 32 samples (64 token rows)/CTA.
__global__ __launch_bounds__(256,1) void k_qa(const U* X,U* C,
    const U* __restrict__ Wq,const float* __restrict__ qb){
  extern __shared__ U sm[];
  U* As=sm; U* Wb=sm+12800;
  float* Qs=(float*)(sm+18944); // 64 x 196: [q64|k64|v64]
  int tid=threadIdx.x,row0=blockIdx.x*64;
  load_act<192,200>(As,X,192,row0,tid,64);
  asm volatile("cp.async.commit_group;");
  int lane=tid&31,warp=tid>>5,wm=warp&3,wn=warp>>2,gid=lane>>2,t4=lane&3;
  for(int h=0;h<3;h++){
    float acc[12][4];
    gemm_bf<192,12,200>(acc,As,Wq+h*36864,Wb,tid);
    #pragma unroll
    for(int nt=0;nt<12;nt++){
      int n=wn*96+nt*8+2*t4,m=wm*16+gid;
      int ib=(n>>6)*192+h*64+(n&63);
      float b0=qb[ib],b1=qb[ib+1];
      Qs[m*196+n]=acc[nt][0]+b0;     Qs[m*196+n+1]=acc[nt][1]+b1;
      Qs[(m+8)*196+n]=acc[nt][2]+b0; Qs[(m+8)*196+n+1]=acc[nt][3]+b1;
    }
    __syncthreads();
    #pragma unroll
    for(int i=0;i<4;i++){
      int r0=(warp*4+i)*2,r1=r0+1;
      float2 q0=*(float2*)(Qs+r0*196+2*lane),q1=*(float2*)(Qs+r1*196+2*lane);
      float2 k0=*(float2*)(Qs+r0*196+64+2*lane),k1=*(float2*)(Qs+r1*196+64+2*lane);
      float pp=q0.x*k0.x+q0.y*k0.y,pt=q0.x*k1.x+q0.y*k1.y;
      float tp=q1.x*k0.x+q1.y*k0.y,tt=q1.x*k1.x+q1.y*k1.y;
      #pragma unroll
      for(int x=16;x>0;x>>=1){pp+=__shfl_xor_sync(~0u,pp,x);pt+=__shfl_xor_sync(~0u,pt,x);
        tp+=__shfl_xor_sync(~0u,tp,x);tt+=__shfl_xor_sync(~0u,tt,x);}
      pp*=0.125f;pt*=0.125f;tp*=0.125f;tt*=0.125f;
      float m0=fmaxf(pp,pt),e0=expf(pp-m0),e1=expf(pt-m0),iv=1.f/(e0+e1);
      float m1=fmaxf(tp,tt),f0=expf(tp-m1),f1=expf(tt-m1),jv=1.f/(f0+f1);
      float a00=e0*iv,a01=e1*iv,a10=f0*jv,a11=f1*jv;
      float2 v0=*(float2*)(Qs+r0*196+128+2*lane),v1=*(float2*)(Qs+r1*196+128+2*lane);
      U hw,lw;
      split2(a00*v0.x+a01*v1.x,a00*v0.y+a01*v1.y,hw,lw);
      *(uint2*)(C+(long)(row0+r0)*192+(h*32+lane)*2)=make_uint2(hw,lw);
      split2(a10*v0.x+a11*v1.x,a10*v0.y+a11*v1.y,hw,lw);
      *(uint2*)(C+(long)(row0+r1)*192+(h*32+lane)*2)=make_uint2(hw,lw);
    }
    __syncthreads();
  }
}

// GEMM(192 out) + residual + LN (+ optional token-pair pooling)
template<int KTOT,int POOL>
__global__ __launch_bounds__(256,(KTOT==192?2:1)) void k_ln(const U* X,int xs2,
    const U* R,const U* __restrict__ Wpk,const float* __restrict__ bias,
    const float* __restrict__ lg,const float* __restrict__ lb,U* O){
  extern __shared__ U sm[];
  constexpr int ALD=KTOT+8;
  U* As=sm; U* Wb=sm+64*ALD;
  int tid=threadIdx.x,row0=blockIdx.x*64;
  load_act<KTOT,ALD>(As,X,xs2,row0,tid,64);
  asm volatile("cp.async.commit_group;");
  float acc[12][4];
  gemm_bf<KTOT,12,ALD>(acc,As,Wpk,Wb,tid);
  float* Ys=(float*)sm;  // reuse A region
  int lane=tid&31,warp=tid>>5,wm=warp&3,wn=warp>>2,gid=lane>>2,t4=lane&3;
  #pragma unroll
  for(int nt=0;nt<12;nt++){
    int n=wn*96+nt*8+2*t4,m=wm*16+gid;
    float b0=bias[n],b1=bias[n+1];
    uint2 rr=*(const uint2*)(R+(long)(row0+m)*192+n);
    float2 r=un2(rr.x,rr.y);
    Ys[m*196+n]=acc[nt][0]+b0+r.x; Ys[m*196+n+1]=acc[nt][1]+b1+r.y;
    rr=*(const uint2*)(R+(long)(row0+m+8)*192+n);
    r=un2(rr.x,rr.y);
    Ys[(m+8)*196+n]=acc[nt][2]+b0+r.x; Ys[(m+8)*196+n+1]=acc[nt][3]+b1+r.y;
  }
  __syncthreads();
  for(int r8=0;r8<8;r8++){
    int r=warp*8+r8;
    float s=0.f,s2=0.f;
    #pragma unroll
    for(int i=0;i<6;i++){float v=Ys[r*196+lane+32*i]; s+=v; s2+=v*v;}
    #pragma unroll
    for(int o=16;o>0;o>>=1){s+=__shfl_xor_sync(~0u,s,o); s2+=__shfl_xor_sync(~0u,s2,o);}
    float mu=s*(1.f/192.f),rs=rsqrtf(s2*(1.f/192.f)-mu*mu+1e-5f);
    #pragma unroll
    for(int i=0;i<3;i++){
      int w=lane+32*i;
      float v0=(Ys[r*196+2*w]-mu)*rs*lg[2*w]+lb[2*w];
      float v1=(Ys[r*196+2*w+1]-mu)*rs*lg[2*w+1]+lb[2*w+1];
      if(POOL){Ys[r*196+2*w]=v0; Ys[r*196+2*w+1]=v1;}
      else{U hw,lw; split2(v0,v1,hw,lw);
        *(uint2*)(O+(long)(row0+r)*192+2*w)=make_uint2(hw,lw);}
    }
  }
  if(POOL){
    __syncthreads();
    for(int idx=tid;idx<32*96;idx+=blockDim.x){
      int i=idx/96,w=idx%96;
      float v0=0.5f*(Ys[(2*i)*196+2*w]+Ys[(2*i+1)*196+2*w]);
      float v1=0.5f*(Ys[(2*i)*196+2*w+1]+Ys[(2*i+1)*196+2*w+1]);
      U hw,lw; split2(v0,v1,hw,lw);
      *(uint2*)(O+(long)(row0/2+i)*192+2*w)=make_uint2(hw,lw);
    }
  }
}

// fused head: cls1(relu)->logits+sigmoid, fp->L2 normalize. 64 samples/CTA.
__global__ __launch_bounds__(256,1) void k_head(const U* X,
    const U* __restrict__ Wc1,const float* __restrict__ c1b,
    const U* __restrict__ Wfp,const float* __restrict__ fpb,
    const float* __restrict__ c2w,const float* __restrict__ c2b,
    float* __restrict__ out,int B){
  extern __shared__ U sm[];
  U* As=sm; U* Wb=sm+12800;
  float* Hs=(float*)(sm+18944);
  int tid=threadIdx.x,row0=blockIdx.x*64;
  load_act<192,200>(As,X,192,row0,tid,64);
  asm volatile("cp.async.commit_group;");
  int lane=tid&31,warp=tid>>5,wm=warp&3,wn=warp>>2,gid=lane>>2,t4=lane&3;
  {
    float acc[12][4];
    gemm_bf<192,12,200>(acc,As,Wc1,Wb,tid);
    #pragma unroll
    for(int nt=0;nt<12;nt++){
      int n=wn*96+nt*8+2*t4,m=wm*16+gid;
      Hs[m*196+n]      =fmaxf(acc[nt][0]+c1b[n],0.f);
      Hs[m*196+n+1]    =fmaxf(acc[nt][1]+c1b[n+1],0.f);
      Hs[(m+8)*196+n]  =fmaxf(acc[nt][2]+c1b[n],0.f);
      Hs[(m+8)*196+n+1]=fmaxf(acc[nt][3]+c1b[n+1],0.f);
    }
  }
  __syncthreads();
  for(int i=0;i<8;i++){
    int r=warp*8+i;
    float d0=0.f,d1=0.f,d2=0.f;
    #pragma unroll
    for(int j=0;j<6;j++){int c=lane+32*j; float v=Hs[r*196+c];
      d0+=v*c2w[c]; d1+=v*c2w[192+c]; d2+=v*c2w[384+c];}
    #pragma unroll
    for(int x=16;x>0;x>>=1){d0+=__shfl_xor_sync(~0u,d0,x);d1+=__shfl_xor_sync(~0u,d1,x);d2+=__shfl_xor_sync(~0u,d2,x);}
    if(lane==0){
      long s=row0+r;
      out[s]     =1.f/(1.f+expf(-(d0+c2b[0])));
      out[B+s]   =1.f/(1.f+expf(-(d1+c2b[1])));
      out[2L*B+s]=1.f/(1.f+expf(-(d2+c2b[2])));
    }
  }
  __syncthreads();
  {
    float acc[8][4];
    gemm_bf<192,8,200>(acc,As,Wfp,Wb,tid);
    #pragma unroll
    for(int nt=0;nt<8;nt++){
      int n=wn*64+nt*8+2*t4,m=wm*16+gid;
      Hs[m*132+n]      =acc[nt][0]+fpb[n];   Hs[m*132+n+1]    =acc[nt][1]+fpb[n+1];
      Hs[(m+8)*132+n]  =acc[nt][2]+fpb[n];   Hs[(m+8)*132+n+1]=acc[nt][3]+fpb[n+1];
    }
  }
  __syncthreads();
  for(int i=0;i<8;i++){
    int r=warp*8+i;
    float s2=0.f;
    #pragma unroll
    for(int j=0;j<4;j++){float v=Hs[r*132+lane+32*j]; s2+=v*v;}
    #pragma unroll
    for(int o=16;o>0;o>>=1) s2+=__shfl_xor_sync(~0u,s2,o);
    float sc=1.f/fmaxf(sqrtf(s2),1e-12f);
    #pragma unroll
    for(int j=0;j<4;j++){int c=lane+32*j; out[3L*B+(long)(row0+r)*128+c]=Hs[r*132+c]*sc;}
  }
}

extern "C" void kernel_launch(void* const* d_in,const int* in_sizes,int n_in,void* d_out,int out_size){
  const float* perc=(const float*)d_in[0];
  const float* tech=(const float*)d_in[1];
  const float* Wp=(const float*)d_in[2];  const float* bp=(const float*)d_in[3];
  const float* Wt=(const float*)d_in[4];  const float* bt=(const float*)d_in[5];
  const float* in_w=(const float*)d_in[6];const float* in_b=(const float*)d_in[7];
  const float* ow=(const float*)d_in[8];  const float* ob=(const float*)d_in[9];
  const float* f1w=(const float*)d_in[10];const float* f1b=(const float*)d_in[11];
  const float* f2w=(const float*)d_in[12];const float* f2b=(const float*)d_in[13];
  const float* l1g=(const float*)d_in[14];const float* l1b=(const float*)d_in[15];
  const float* l2g=(const float*)d_in[16];const float* l2b=(const float*)d_in[17];
  const float* c1w=(const float*)d_in[18];const float* c1b=(const float*)d_in[19];
  const float* c2w=(const float*)d_in[20];const float* c2b=(const float*)d_in[21];
  const float* fpw=(const float*)d_in[22];const float* fpb=(const float*)d_in[23];
  int B=in_sizes[0]/192;
  float* out=(float*)d_out;

  U *wpk,*seq,*ctx,*x,*hh,*z;
  cudaGetSymbolAddress((void**)&wpk,g_wpk);
  cudaGetSymbolAddress((void**)&seq,g_seq);
  cudaGetSymbolAddress((void**)&ctx,g_ctx);
  cudaGetSymbolAddress((void**)&x,g_x);
  cudaGetSymbolAddress((void**)&hh,g_h);
  cudaGetSymbolAddress((void**)&z,g_z);

  const int S192=36864;
  const int O_WP=0,O_WT=36864,O_QA=73728,O_OW=184320,O_F1=221184,O_F2=294912,O_C1=368640,O_FP=405504;

  Jobs J;
  J.j[0]={Wp, 192,192,192,64, O_WP};
  J.j[1]={Wt, 192,192,192,64, O_WT};
  J.j[2]={in_w+0*64*192,192,192,192,192,O_QA};
  J.j[3]={in_w+1*64*192,192,192,192,192,O_QA+S192};
  J.j[4]={in_w+2*64*192,192,192,192,192,O_QA+2*S192};
  J.j[5]={ow, 192,192,192,64, O_OW};
  J.j[6]={f1w,192,192,192,64, O_F1};
  J.j[7]={f1w+192*192,192,192,192,64,O_F1+S192};
  J.j[8]={f2w,384,192,384,64, O_F2};
  J.j[9]={c1w,192,192,192,64, O_C1};
  J.j[10]={fpw,192,128,192,64,O_FP};

  const int SZP=75776,SZQA=125952,SZL2=124928,SZH=125952;
  cudaFuncSetAttribute(k_gemm192<0>,cudaFuncAttributeMaxDynamicSharedMemorySize,SZP);
  cudaFuncSetAttribute(k_gemm192<1>,cudaFuncAttributeMaxDynamicSharedMemorySize,SZP);
  cudaFuncSetAttribute(k_qa,        cudaFuncAttributeMaxDynamicSharedMemorySize,SZQA);
  cudaFuncSetAttribute(k_ln<192,0>, cudaFuncAttributeMaxDynamicSharedMemorySize,SZP);
  cudaFuncSetAttribute(k_ln<384,1>, cudaFuncAttributeMaxDynamicSharedMemorySize,SZL2);
  cudaFuncSetAttribute(k_head,      cudaFuncAttributeMaxDynamicSharedMemorySize,SZH);

  k_splitall<<<dim3(24,11),256>>>(J);

  int Rs=B/64,R2=2*B/64;
  // 1) projections -> seq (token-interleaved rows: sample row stride 384 words, tech at +192)
  k_gemm192<1><<<Rs,256,SZP>>>(perc,0,0,seq,    384,wpk+O_WP,S192,bp,0);
  k_gemm192<1><<<Rs,256,SZP>>>(tech,0,0,seq+192,384,wpk+O_WT,S192,bt,0);
  // 2) qkv + attention -> ctx
  k_qa<<<R2,256,SZQA>>>(seq,ctx,wpk+O_QA,in_b);
  // 3) out-proj + residual + LN1 -> x
  k_ln<192,0><<<R2,256,SZP>>>(ctx,192,seq,wpk+O_OW,ob,l1g,l1b,x);
  // 4) FFN1 relu -> h (2 col-chunks; hidden row = 384 words)
  k_gemm192<0><<<dim3(R2,2),256,SZP>>>(0,x,192,hh,384,wpk+O_F1,S192,f1b,1);
  // 5) FFN2 + residual + LN2 + pool -> z
  k_ln<384,1><<<R2,256,SZL2>>>(hh,384,x,wpk+O_F2,f2b,l2g,l2b,z);
  // 6) heads -> out
  k_head<<<Rs,256,SZH>>>(z,wpk+O_C1,c1b,wpk+O_FP,fpb,c2w,c2b,out,B);
}